// round 1
// baseline (speedup 1.0000x reference)
#include <cuda_runtime.h>
#include <cuda_bf16.h>
#include <cstdint>

#define N_NODES 51200
#define N_EDGES 2048000
#define F_IN    400
#define F_HID   128
#define RO_OUT  8
#define N_GRAPHS 128
#define FC1_IN  3200
#define FC1_OUT 400
#define BN_EPS  1e-5f

// ---------------- device scratch (static, allocation-free) ----------------
__device__ float g_bufA[(size_t)N_NODES * F_HID];
__device__ float g_bufB[(size_t)N_NODES * F_HID];
__device__ float g_deg[N_NODES];
__device__ float g_dinv[N_NODES];
__device__ int   g_cnt[N_NODES];
__device__ int   g_off[N_NODES + 1];
__device__ int   g_ptr[N_NODES];
__device__ int   g_erow[N_EDGES];
__device__ float g_enorm[N_EDGES];
__device__ float g_feats[(size_t)N_NODES * RO_OUT];
__device__ float g_z[N_GRAPHS * FC1_OUT];
__device__ float g_mu[FC1_OUT];
__device__ float g_rstd[FC1_OUT];

__device__ __forceinline__ float mishf(float x) {
    // softplus computed as logaddexp(x, 0) = max(x,0) + log1p(exp(-|x|))  (matches jax)
    float sp = fmaxf(x, 0.0f) + log1pf(expf(-fabsf(x)));
    return x * tanhf(sp);
}

// ---------------- graph preprocessing ----------------
__global__ void k_init_deg_cnt() {
    int i = blockIdx.x * blockDim.x + threadIdx.x;
    if (i < N_NODES) { g_deg[i] = 1.0f; g_cnt[i] = 0; }   // self-loop weight 1
}

__global__ void k_edge_pass1(const int* __restrict__ col, const float* __restrict__ ew) {
    int e = blockIdx.x * blockDim.x + threadIdx.x;
    if (e < N_EDGES) {
        int c = col[e];
        atomicAdd(&g_deg[c], ew[e]);
        atomicAdd(&g_cnt[c], 1);
    }
}

__global__ void k_dinv() {
    int i = blockIdx.x * blockDim.x + threadIdx.x;
    if (i < N_NODES) {
        float d = g_deg[i];
        g_dinv[i] = (d > 0.0f) ? rsqrtf(d) : 0.0f;
    }
}

// single block, 1024 threads: exclusive prefix sum of g_cnt -> g_off, g_ptr
__global__ void k_scan() {
    __shared__ int s[1024];
    const int PER = N_NODES / 1024;  // 50
    int t = threadIdx.x;
    int base = t * PER;
    int sum = 0;
    for (int j = 0; j < PER; ++j) sum += g_cnt[base + j];
    s[t] = sum;
    __syncthreads();
    // inclusive scan (Hillis-Steele)
    for (int d = 1; d < 1024; d <<= 1) {
        int v = 0;
        if (t >= d) v = s[t - d];
        __syncthreads();
        if (t >= d) s[t] += v;
        __syncthreads();
    }
    int prefix = (t == 0) ? 0 : s[t - 1];
    int run = prefix;
    for (int j = 0; j < PER; ++j) {
        g_off[base + j] = run;
        g_ptr[base + j] = run;
        run += g_cnt[base + j];
    }
    if (t == 1023) g_off[N_NODES] = run;  // == N_EDGES
}

__global__ void k_edge_pass2(const int* __restrict__ row, const int* __restrict__ col,
                             const float* __restrict__ ew) {
    int e = blockIdx.x * blockDim.x + threadIdx.x;
    if (e < N_EDGES) {
        int r = row[e], c = col[e];
        float nrm = g_dinv[r] * ew[e] * g_dinv[c];
        int p = atomicAdd(&g_ptr[c], 1);
        g_erow[p] = r;
        g_enorm[p] = nrm;
    }
}

// ---------------- SGEMM: C[M,128] = A[M,K] @ B[K,128], fp32 ----------------
// BM=128, BN=128 (=full N), BK=8, 256 threads, 8x8 per thread
__global__ __launch_bounds__(256) void k_sgemm(const float* __restrict__ A,
                                               const float* __restrict__ B,
                                               float* __restrict__ C, int K) {
    __shared__ float As[8][128];
    __shared__ float Bs[8][128];
    int tid = threadIdx.x;
    int row0 = blockIdx.x * 128;
    int ty = tid >> 4, tx = tid & 15;
    int ar = tid >> 1;            // 0..127
    int ak = (tid & 1) * 4;       // 0 or 4
    int br = tid >> 5;            // 0..7
    int bc = (tid & 31) * 4;      // 0..124

    float acc[8][8];
    #pragma unroll
    for (int i = 0; i < 8; ++i)
        #pragma unroll
        for (int j = 0; j < 8; ++j) acc[i][j] = 0.0f;

    for (int k0 = 0; k0 < K; k0 += 8) {
        float4 av = *reinterpret_cast<const float4*>(&A[(size_t)(row0 + ar) * K + k0 + ak]);
        float4 bv = *reinterpret_cast<const float4*>(&B[(size_t)(k0 + br) * 128 + bc]);
        As[ak + 0][ar] = av.x; As[ak + 1][ar] = av.y;
        As[ak + 2][ar] = av.z; As[ak + 3][ar] = av.w;
        *reinterpret_cast<float4*>(&Bs[br][bc]) = bv;
        __syncthreads();
        #pragma unroll
        for (int kk = 0; kk < 8; ++kk) {
            float a[8], b[8];
            #pragma unroll
            for (int i = 0; i < 8; ++i) a[i] = As[kk][ty * 8 + i];
            #pragma unroll
            for (int j = 0; j < 8; ++j) b[j] = Bs[kk][tx * 8 + j];
            #pragma unroll
            for (int i = 0; i < 8; ++i)
                #pragma unroll
                for (int j = 0; j < 8; ++j)
                    acc[i][j] = fmaf(a[i], b[j], acc[i][j]);
        }
        __syncthreads();
    }
    #pragma unroll
    for (int i = 0; i < 8; ++i) {
        float4* cp = reinterpret_cast<float4*>(&C[(size_t)(row0 + ty * 8 + i) * 128 + tx * 8]);
        cp[0] = make_float4(acc[i][0], acc[i][1], acc[i][2], acc[i][3]);
        cp[1] = make_float4(acc[i][4], acc[i][5], acc[i][6], acc[i][7]);
    }
}

// ---------------- per-node aggregation: out = mish(selfloop + scatter + bias) ----------------
__global__ __launch_bounds__(128) void k_aggregate(const float* __restrict__ h,
                                                   const float* __restrict__ bias,
                                                   float* __restrict__ out) {
    int i = blockIdx.x;
    int f = threadIdx.x;  // 0..127
    __shared__ int   s_row[128];
    __shared__ float s_nrm[128];
    float di = g_dinv[i];
    float acc = di * di * h[(size_t)i * 128 + f];   // self loop: norm = dinv^2
    int e0 = g_off[i], e1 = g_off[i + 1];
    for (int base = e0; base < e1; base += 128) {
        int n = min(128, e1 - base);
        if (f < n) { s_row[f] = g_erow[base + f]; s_nrm[f] = g_enorm[base + f]; }
        __syncthreads();
        #pragma unroll 4
        for (int j = 0; j < n; ++j)
            acc = fmaf(s_nrm[j], h[(size_t)s_row[j] * 128 + f], acc);
        __syncthreads();
    }
    out[(size_t)i * 128 + f] = mishf(acc + bias[f]);
}

// ---------------- readout: feats = mish(h @ ro_w + ro_b), [N,8] ----------------
__global__ void k_readout(const float* __restrict__ h, const float* __restrict__ w,
                          const float* __restrict__ b) {
    int g = blockIdx.x * blockDim.x + threadIdx.x;
    if (g >= N_NODES * RO_OUT) return;
    int i = g >> 3, j = g & 7;
    const float4* hp = reinterpret_cast<const float4*>(h + (size_t)i * 128);
    float acc = 0.0f;
    #pragma unroll
    for (int k4 = 0; k4 < 32; ++k4) {
        float4 v = hp[k4];
        acc = fmaf(v.x, w[(k4 * 4 + 0) * 8 + j], acc);
        acc = fmaf(v.y, w[(k4 * 4 + 1) * 8 + j], acc);
        acc = fmaf(v.z, w[(k4 * 4 + 2) * 8 + j], acc);
        acc = fmaf(v.w, w[(k4 * 4 + 3) * 8 + j], acc);
    }
    g_feats[g] = mishf(acc + b[j]);
}

// ---------------- fc1: z[g][c] = feats[g,:] . W[:,c] + b[c] ----------------
__global__ __launch_bounds__(400) void k_fc1(const float* __restrict__ W,
                                             const float* __restrict__ b) {
    int g = blockIdx.x;
    int c = threadIdx.x;  // 0..399
    __shared__ float s[FC1_IN];
    for (int k = c; k < FC1_IN; k += FC1_OUT)
        s[k] = g_feats[(size_t)g * FC1_IN + k];
    __syncthreads();
    float acc = b[c];
    #pragma unroll 4
    for (int k = 0; k < FC1_IN; ++k)
        acc = fmaf(s[k], W[(size_t)k * FC1_OUT + c], acc);
    g_z[g * FC1_OUT + c] = acc;
}

// ---------------- batchnorm stats (two-pass for accuracy) ----------------
__global__ void k_bn_stats() {
    int c = blockIdx.x * blockDim.x + threadIdx.x;
    if (c >= FC1_OUT) return;
    float s = 0.0f;
    for (int r = 0; r < N_GRAPHS; ++r) s += g_z[r * FC1_OUT + c];
    float m = s * (1.0f / N_GRAPHS);
    float v = 0.0f;
    for (int r = 0; r < N_GRAPHS; ++r) {
        float d = g_z[r * FC1_OUT + c] - m;
        v = fmaf(d, d, v);
    }
    v *= (1.0f / N_GRAPHS);
    g_mu[c] = m;
    g_rstd[c] = rsqrtf(v + BN_EPS);
}

// ---------------- final: logits = mish(bn(z)) @ fc2_w + fc2_b ----------------
__global__ __launch_bounds__(512) void k_final(const float* __restrict__ gamma,
                                               const float* __restrict__ beta,
                                               const float* __restrict__ w2,
                                               const float* __restrict__ b2,
                                               float* __restrict__ out) {
    int g = blockIdx.x;
    int t = threadIdx.x;  // 0..511
    __shared__ float s0[512], s1[512];
    float v0 = 0.0f, v1 = 0.0f;
    if (t < FC1_OUT) {
        float zn = (g_z[g * FC1_OUT + t] - g_mu[t]) * g_rstd[t] * gamma[t] + beta[t];
        float m = mishf(zn);
        v0 = m * w2[t * 2 + 0];
        v1 = m * w2[t * 2 + 1];
    }
    s0[t] = v0; s1[t] = v1;
    __syncthreads();
    for (int d = 256; d > 0; d >>= 1) {
        if (t < d) { s0[t] += s0[t + d]; s1[t] += s1[t + d]; }
        __syncthreads();
    }
    if (t == 0) {
        out[g * 2 + 0] = s0[0] + b2[0];
        out[g * 2 + 1] = s1[0] + b2[1];
    }
}

// ---------------- host launcher ----------------
extern "C" void kernel_launch(void* const* d_in, const int* in_sizes, int n_in,
                              void* d_out, int out_size) {
    const float* x      = (const float*)d_in[0];
    const int*   ei     = (const int*)d_in[1];     // [2, E]
    const float* ea     = (const float*)d_in[2];
    // d_in[3] = batch (implicit: node i -> graph i/400), unused
    const float* w1     = (const float*)d_in[4];
    const float* b1     = (const float*)d_in[5];
    const float* w2     = (const float*)d_in[6];
    const float* b2     = (const float*)d_in[7];
    const float* ro_w   = (const float*)d_in[8];
    const float* ro_b   = (const float*)d_in[9];
    const float* fc1_w  = (const float*)d_in[10];
    const float* fc1_b  = (const float*)d_in[11];
    const float* gamma  = (const float*)d_in[12];
    const float* beta   = (const float*)d_in[13];
    const float* fc2_w  = (const float*)d_in[14];
    const float* fc2_b  = (const float*)d_in[15];
    float* out = (float*)d_out;

    const int* row = ei;
    const int* col = ei + N_EDGES;

    float *pA = nullptr, *pB = nullptr;
    cudaGetSymbolAddress((void**)&pA, g_bufA);
    cudaGetSymbolAddress((void**)&pB, g_bufB);

    // graph preprocessing (shared by both conv layers)
    k_init_deg_cnt<<<(N_NODES + 255) / 256, 256>>>();
    k_edge_pass1<<<(N_EDGES + 255) / 256, 256>>>(col, ea);
    k_dinv<<<(N_NODES + 255) / 256, 256>>>();
    k_scan<<<1, 1024>>>();
    k_edge_pass2<<<(N_EDGES + 255) / 256, 256>>>(row, col, ea);

    // conv1: bufA = x @ W1 ; bufB = mish(agg(bufA) + b1)
    k_sgemm<<<N_NODES / 128, 256>>>(x, w1, pA, F_IN);
    k_aggregate<<<N_NODES, 128>>>(pA, b1, pB);

    // conv2: bufA = bufB @ W2 ; bufB = mish(agg(bufA) + b2)
    k_sgemm<<<N_NODES / 128, 256>>>(pB, w2, pA, F_HID);
    k_aggregate<<<N_NODES, 128>>>(pA, b2, pB);

    // readout -> feats [N, 8]
    k_readout<<<(N_NODES * RO_OUT + 255) / 256, 256>>>(pB, ro_w, ro_b);

    // fc1 -> z [128, 400]
    k_fc1<<<N_GRAPHS, FC1_OUT>>>(fc1_w, fc1_b);

    // batchnorm stats + final head
    k_bn_stats<<<2, 256>>>();
    k_final<<<N_GRAPHS, 512>>>(gamma, beta, fc2_w, fc2_b, out);
}

// round 2
// speedup vs baseline: 1.1176x; 1.1176x over previous
#include <cuda_runtime.h>
#include <cuda_bf16.h>
#include <cstdint>

#define N_NODES 51200
#define N_EDGES 2048000
#define F_IN    400
#define F_HID   128
#define RO_OUT  8
#define N_GRAPHS 128
#define FC1_IN  3200
#define FC1_OUT 400
#define BN_EPS  1e-5f
#define SCAN_BLOCKS 50   // 50 * 1024 = 51200

// ---------------- device scratch (static, allocation-free) ----------------
__device__ float g_bufA[(size_t)N_NODES * F_HID];
__device__ float g_bufB[(size_t)N_NODES * F_HID];
__device__ float g_deg[N_NODES];
__device__ float g_dinv[N_NODES];
__device__ int   g_cnt[N_NODES];
__device__ int   g_off[N_NODES + 1];
__device__ int   g_ptr[N_NODES];
__device__ int   g_part[SCAN_BLOCKS];
__device__ int   g_partoff[SCAN_BLOCKS];
__device__ int   g_erow[N_EDGES];
__device__ float g_enorm[N_EDGES];
__device__ float g_feats[(size_t)N_NODES * RO_OUT];
__device__ float g_z[N_GRAPHS * FC1_OUT];
__device__ float g_mu[FC1_OUT];
__device__ float g_rstd[FC1_OUT];

__device__ __forceinline__ float mishf(float x) {
    float sp = fmaxf(x, 0.0f) + log1pf(expf(-fabsf(x)));
    return x * tanhf(sp);
}

// ---------------- graph preprocessing ----------------
__global__ void k_init_deg_cnt() {
    int i = blockIdx.x * blockDim.x + threadIdx.x;
    if (i < N_NODES) { g_deg[i] = 1.0f; g_cnt[i] = 0; }   // self-loop weight 1
}

__global__ void k_edge_pass1(const int* __restrict__ col, const float* __restrict__ ew) {
    int e = blockIdx.x * blockDim.x + threadIdx.x;
    if (e < N_EDGES) {
        int c = col[e];
        atomicAdd(&g_deg[c], ew[e]);
        atomicAdd(&g_cnt[c], 1);
    }
}

// phase 1: per-1024-chunk reduction of g_cnt + dinv computation (fused)
__global__ __launch_bounds__(1024) void k_part_dinv() {
    int b = blockIdx.x, t = threadIdx.x;
    int i = b * 1024 + t;
    float d = g_deg[i];
    g_dinv[i] = (d > 0.0f) ? rsqrtf(d) : 0.0f;
    int v = g_cnt[i];
    // warp reduce
    #pragma unroll
    for (int dlt = 16; dlt > 0; dlt >>= 1) v += __shfl_down_sync(~0u, v, dlt);
    __shared__ int ws[32];
    if ((t & 31) == 0) ws[t >> 5] = v;
    __syncthreads();
    if (t < 32) {
        int x = ws[t];
        #pragma unroll
        for (int dlt = 16; dlt > 0; dlt >>= 1) x += __shfl_down_sync(~0u, x, dlt);
        if (t == 0) g_part[b] = x;
    }
}

// phase 2: exclusive scan of 50 partials (trivial)
__global__ void k_scan_part() {
    if (threadIdx.x == 0) {
        int run = 0;
        for (int b = 0; b < SCAN_BLOCKS; ++b) {
            g_partoff[b] = run;
            run += g_part[b];
        }
        g_off[N_NODES] = run;   // == N_EDGES
    }
}

// phase 3: per-block exclusive scan (shuffle-based) + add partial offset
__global__ __launch_bounds__(1024) void k_scan_blocks() {
    int b = blockIdx.x, t = threadIdx.x;
    int i = b * 1024 + t;
    int v = g_cnt[i];
    int lane = t & 31, w = t >> 5;
    int x = v;
    #pragma unroll
    for (int dlt = 1; dlt < 32; dlt <<= 1) {
        int y = __shfl_up_sync(~0u, x, dlt);
        if (lane >= dlt) x += y;
    }
    __shared__ int ws[32];
    if (lane == 31) ws[w] = x;
    __syncthreads();
    if (w == 0) {
        int y = ws[lane];
        #pragma unroll
        for (int dlt = 1; dlt < 32; dlt <<= 1) {
            int z = __shfl_up_sync(~0u, y, dlt);
            if (lane >= dlt) y += z;
        }
        ws[lane] = y;
    }
    __syncthreads();
    int incl = x + (w > 0 ? ws[w - 1] : 0);
    int excl = incl - v + g_partoff[b];
    g_off[i] = excl;
    g_ptr[i] = excl;
}

__global__ void k_edge_pass2(const int* __restrict__ row, const int* __restrict__ col,
                             const float* __restrict__ ew) {
    int e = blockIdx.x * blockDim.x + threadIdx.x;
    if (e < N_EDGES) {
        int r = row[e], c = col[e];
        float nrm = g_dinv[r] * ew[e] * g_dinv[c];
        int p = atomicAdd(&g_ptr[c], 1);
        g_erow[p] = r;
        g_enorm[p] = nrm;
    }
}

// ---------------- SGEMM: C[M,128] = A[M,K] @ B[K,128], fp32 ----------------
__global__ __launch_bounds__(256) void k_sgemm(const float* __restrict__ A,
                                               const float* __restrict__ B,
                                               float* __restrict__ C, int K) {
    __shared__ float As[8][128];
    __shared__ float Bs[8][128];
    int tid = threadIdx.x;
    int row0 = blockIdx.x * 128;
    int ty = tid >> 4, tx = tid & 15;
    int ar = tid >> 1;
    int ak = (tid & 1) * 4;
    int br = tid >> 5;
    int bc = (tid & 31) * 4;

    float acc[8][8];
    #pragma unroll
    for (int i = 0; i < 8; ++i)
        #pragma unroll
        for (int j = 0; j < 8; ++j) acc[i][j] = 0.0f;

    for (int k0 = 0; k0 < K; k0 += 8) {
        float4 av = *reinterpret_cast<const float4*>(&A[(size_t)(row0 + ar) * K + k0 + ak]);
        float4 bv = *reinterpret_cast<const float4*>(&B[(size_t)(k0 + br) * 128 + bc]);
        As[ak + 0][ar] = av.x; As[ak + 1][ar] = av.y;
        As[ak + 2][ar] = av.z; As[ak + 3][ar] = av.w;
        *reinterpret_cast<float4*>(&Bs[br][bc]) = bv;
        __syncthreads();
        #pragma unroll
        for (int kk = 0; kk < 8; ++kk) {
            float a[8], b[8];
            #pragma unroll
            for (int i = 0; i < 8; ++i) a[i] = As[kk][ty * 8 + i];
            #pragma unroll
            for (int j = 0; j < 8; ++j) b[j] = Bs[kk][tx * 8 + j];
            #pragma unroll
            for (int i = 0; i < 8; ++i)
                #pragma unroll
                for (int j = 0; j < 8; ++j)
                    acc[i][j] = fmaf(a[i], b[j], acc[i][j]);
        }
        __syncthreads();
    }
    #pragma unroll
    for (int i = 0; i < 8; ++i) {
        float4* cp = reinterpret_cast<float4*>(&C[(size_t)(row0 + ty * 8 + i) * 128 + tx * 8]);
        cp[0] = make_float4(acc[i][0], acc[i][1], acc[i][2], acc[i][3]);
        cp[1] = make_float4(acc[i][4], acc[i][5], acc[i][6], acc[i][7]);
    }
}

// ---------------- per-node aggregation: out = mish(selfloop + scatter + bias) ----------------
__global__ __launch_bounds__(128) void k_aggregate(const float* __restrict__ h,
                                                   const float* __restrict__ bias,
                                                   float* __restrict__ out) {
    int i = blockIdx.x;
    int f = threadIdx.x;
    __shared__ int   s_row[128];
    __shared__ float s_nrm[128];
    float di = g_dinv[i];
    float acc = di * di * h[(size_t)i * 128 + f];
    int e0 = g_off[i], e1 = g_off[i + 1];
    for (int base = e0; base < e1; base += 128) {
        int n = min(128, e1 - base);
        if (f < n) { s_row[f] = g_erow[base + f]; s_nrm[f] = g_enorm[base + f]; }
        __syncthreads();
        #pragma unroll 4
        for (int j = 0; j < n; ++j)
            acc = fmaf(s_nrm[j], h[(size_t)s_row[j] * 128 + f], acc);
        __syncthreads();
    }
    out[(size_t)i * 128 + f] = mishf(acc + bias[f]);
}

// ---------------- readout: feats = mish(h @ ro_w + ro_b), [N,8] ----------------
__global__ void k_readout(const float* __restrict__ h, const float* __restrict__ w,
                          const float* __restrict__ b) {
    int g = blockIdx.x * blockDim.x + threadIdx.x;
    if (g >= N_NODES * RO_OUT) return;
    int i = g >> 3, j = g & 7;
    const float4* hp = reinterpret_cast<const float4*>(h + (size_t)i * 128);
    float acc = 0.0f;
    #pragma unroll
    for (int k4 = 0; k4 < 32; ++k4) {
        float4 v = hp[k4];
        acc = fmaf(v.x, w[(k4 * 4 + 0) * 8 + j], acc);
        acc = fmaf(v.y, w[(k4 * 4 + 1) * 8 + j], acc);
        acc = fmaf(v.z, w[(k4 * 4 + 2) * 8 + j], acc);
        acc = fmaf(v.w, w[(k4 * 4 + 3) * 8 + j], acc);
    }
    g_feats[g] = mishf(acc + b[j]);
}

// ---------------- fc1: 2 graphs per block, W element reused for both ----------------
__global__ __launch_bounds__(400) void k_fc1(const float* __restrict__ W,
                                             const float* __restrict__ b) {
    int g0 = blockIdx.x * 2;
    int c = threadIdx.x;  // 0..399
    __shared__ float s0[FC1_IN], s1[FC1_IN];
    for (int k = c; k < FC1_IN; k += FC1_OUT) {
        s0[k] = g_feats[(size_t)g0 * FC1_IN + k];
        s1[k] = g_feats[(size_t)(g0 + 1) * FC1_IN + k];
    }
    __syncthreads();
    float a0 = b[c], a1 = a0;
    #pragma unroll 4
    for (int k = 0; k < FC1_IN; ++k) {
        float w = W[(size_t)k * FC1_OUT + c];
        a0 = fmaf(s0[k], w, a0);
        a1 = fmaf(s1[k], w, a1);
    }
    g_z[g0 * FC1_OUT + c] = a0;
    g_z[(g0 + 1) * FC1_OUT + c] = a1;
}

// ---------------- batchnorm stats (two-pass for accuracy) ----------------
__global__ void k_bn_stats() {
    int c = blockIdx.x * blockDim.x + threadIdx.x;
    if (c >= FC1_OUT) return;
    float s = 0.0f;
    for (int r = 0; r < N_GRAPHS; ++r) s += g_z[r * FC1_OUT + c];
    float m = s * (1.0f / N_GRAPHS);
    float v = 0.0f;
    for (int r = 0; r < N_GRAPHS; ++r) {
        float d = g_z[r * FC1_OUT + c] - m;
        v = fmaf(d, d, v);
    }
    v *= (1.0f / N_GRAPHS);
    g_mu[c] = m;
    g_rstd[c] = rsqrtf(v + BN_EPS);
}

// ---------------- final: logits = mish(bn(z)) @ fc2_w + fc2_b ----------------
__global__ __launch_bounds__(512) void k_final(const float* __restrict__ gamma,
                                               const float* __restrict__ beta,
                                               const float* __restrict__ w2,
                                               const float* __restrict__ b2,
                                               float* __restrict__ out) {
    int g = blockIdx.x;
    int t = threadIdx.x;
    __shared__ float s0[512], s1[512];
    float v0 = 0.0f, v1 = 0.0f;
    if (t < FC1_OUT) {
        float zn = (g_z[g * FC1_OUT + t] - g_mu[t]) * g_rstd[t] * gamma[t] + beta[t];
        float m = mishf(zn);
        v0 = m * w2[t * 2 + 0];
        v1 = m * w2[t * 2 + 1];
    }
    s0[t] = v0; s1[t] = v1;
    __syncthreads();
    for (int d = 256; d > 0; d >>= 1) {
        if (t < d) { s0[t] += s0[t + d]; s1[t] += s1[t + d]; }
        __syncthreads();
    }
    if (t == 0) {
        out[g * 2 + 0] = s0[0] + b2[0];
        out[g * 2 + 1] = s1[0] + b2[1];
    }
}

// ---------------- host launcher ----------------
extern "C" void kernel_launch(void* const* d_in, const int* in_sizes, int n_in,
                              void* d_out, int out_size) {
    const float* x      = (const float*)d_in[0];
    const int*   ei     = (const int*)d_in[1];
    const float* ea     = (const float*)d_in[2];
    const float* w1     = (const float*)d_in[4];
    const float* b1     = (const float*)d_in[5];
    const float* w2     = (const float*)d_in[6];
    const float* b2     = (const float*)d_in[7];
    const float* ro_w   = (const float*)d_in[8];
    const float* ro_b   = (const float*)d_in[9];
    const float* fc1_w  = (const float*)d_in[10];
    const float* fc1_b  = (const float*)d_in[11];
    const float* gamma  = (const float*)d_in[12];
    const float* beta   = (const float*)d_in[13];
    const float* fc2_w  = (const float*)d_in[14];
    const float* fc2_b  = (const float*)d_in[15];
    float* out = (float*)d_out;

    const int* row = ei;
    const int* col = ei + N_EDGES;

    float *pA = nullptr, *pB = nullptr;
    cudaGetSymbolAddress((void**)&pA, g_bufA);
    cudaGetSymbolAddress((void**)&pB, g_bufB);

    // lazy one-time stream/event creation (first call is uncaptured)
    static cudaStream_t s2 = nullptr;
    static cudaEvent_t evFork = nullptr, evJoin = nullptr;
    if (!s2) {
        cudaStreamCreateWithFlags(&s2, cudaStreamNonBlocking);
        cudaEventCreateWithFlags(&evFork, cudaEventDisableTiming);
        cudaEventCreateWithFlags(&evJoin, cudaEventDisableTiming);
    }

    // fork: preprocessing on s2, GEMM1 on main stream, join before aggregation
    cudaEventRecord(evFork, 0);
    cudaStreamWaitEvent(s2, evFork, 0);

    // --- s2: graph preprocessing chain ---
    k_init_deg_cnt<<<(N_NODES + 255) / 256, 256, 0, s2>>>();
    k_edge_pass1<<<(N_EDGES + 255) / 256, 256, 0, s2>>>(col, ea);
    k_part_dinv<<<SCAN_BLOCKS, 1024, 0, s2>>>();
    k_scan_part<<<1, 32, 0, s2>>>();
    k_scan_blocks<<<SCAN_BLOCKS, 1024, 0, s2>>>();
    k_edge_pass2<<<(N_EDGES + 255) / 256, 256, 0, s2>>>(row, col, ea);
    cudaEventRecord(evJoin, s2);

    // --- main stream: GEMM1 runs concurrently ---
    k_sgemm<<<N_NODES / 128, 256>>>(x, w1, pA, F_IN);

    // join
    cudaStreamWaitEvent(0, evJoin, 0);

    // conv1 aggregation + conv2
    k_aggregate<<<N_NODES, 128>>>(pA, b1, pB);
    k_sgemm<<<N_NODES / 128, 256>>>(pB, w2, pA, F_HID);
    k_aggregate<<<N_NODES, 128>>>(pA, b2, pB);

    // readout -> feats [N, 8]
    k_readout<<<(N_NODES * RO_OUT + 255) / 256, 256>>>(pB, ro_w, ro_b);

    // fc1 -> z [128, 400]  (2 graphs per block)
    k_fc1<<<N_GRAPHS / 2, FC1_OUT>>>(fc1_w, fc1_b);

    // batchnorm stats + final head
    k_bn_stats<<<2, 256>>>();
    k_final<<<N_GRAPHS, 512>>>(gamma, beta, fc2_w, fc2_b, out);
}